// round 2
// baseline (speedup 1.0000x reference)
#include <cuda_runtime.h>
#include <math.h>

#define CB 2
#define CT 2048
#define CD 1024
#define CH 16
#define CDK 64
#define CM (CB*CT)   // 4096

// Scratch (device globals: no allocation allowed)
__device__ float g_q[CB*CH*CT*CDK];
__device__ float g_k[CB*CH*CT*CDK];
__device__ float g_v[CB*CH*CT*CDK];
__device__ float g_cat[CM*CD];

// ---------------------------------------------------------------------------
// GEMM: C[m,n] = sum_k A[m,k] * W[n,k]   (both row-major, K-contiguous "NT")
// BM=BN=64, BK=16, 256 threads, 4x4 micro-tile per thread.
// mode 0: plain row-major [M,N] output
// mode 1: RoPE + write to head layout [B,H,T,DK]
// mode 2: no RoPE, write to head layout [B,H,T,DK]
// ---------------------------------------------------------------------------
__global__ __launch_bounds__(256) void gemm_proj(
    const float* __restrict__ A, const float* __restrict__ W,
    float* __restrict__ out, int mode)
{
    __shared__ float As[16][64];
    __shared__ float Bs[16][64];
    const int K = CD;
    int tid = threadIdx.x;
    int tx = tid & 15, ty = tid >> 4;
    int m0 = blockIdx.y * 64, n0 = blockIdx.x * 64;
    int lr = tid >> 2, lc = tid & 3;
    const float* Aptr = A + (size_t)(m0 + lr) * K + lc * 4;
    const float* Wptr = W + (size_t)(n0 + lr) * K + lc * 4;

    float acc[4][4] = {};
    for (int k0 = 0; k0 < K; k0 += 16) {
        float4 av = *(const float4*)(Aptr + k0);
        float4 bv = *(const float4*)(Wptr + k0);
        As[lc*4+0][lr] = av.x; As[lc*4+1][lr] = av.y;
        As[lc*4+2][lr] = av.z; As[lc*4+3][lr] = av.w;
        Bs[lc*4+0][lr] = bv.x; Bs[lc*4+1][lr] = bv.y;
        Bs[lc*4+2][lr] = bv.z; Bs[lc*4+3][lr] = bv.w;
        __syncthreads();
        #pragma unroll
        for (int kk = 0; kk < 16; kk++) {
            float4 a = *(const float4*)&As[kk][ty*4];
            float4 b = *(const float4*)&Bs[kk][tx*4];
            float ar[4] = {a.x, a.y, a.z, a.w};
            float br[4] = {b.x, b.y, b.z, b.w};
            #pragma unroll
            for (int i = 0; i < 4; i++)
                #pragma unroll
                for (int j = 0; j < 4; j++)
                    acc[i][j] += ar[i] * br[j];
        }
        __syncthreads();
    }

    if (mode == 0) {
        #pragma unroll
        for (int i = 0; i < 4; i++) {
            int row = m0 + ty*4 + i;
            float4 v = make_float4(acc[i][0], acc[i][1], acc[i][2], acc[i][3]);
            *(float4*)&out[(size_t)row * CD + n0 + tx*4] = v;
        }
        return;
    }

    #pragma unroll
    for (int i = 0; i < 4; i++) {
        int row = m0 + ty*4 + i;
        int b = row / CT, t = row % CT;
        if (mode == 1) {
            #pragma unroll
            for (int p = 0; p < 2; p++) {
                int e = n0 + tx*4 + 2*p;
                int h = e >> 6, d = e & 63;
                int pidx = d >> 1;
                // inv_freq = 1000^(-pidx/32) = 2^(-pidx/32 * log2(1000))
                float inv = exp2f(-(float)pidx * (9.965784284662087f / 32.0f));
                float ang = (float)t * inv;
                float s, c;
                sincosf(ang, &s, &c);
                float xe = acc[i][2*p], xo = acc[i][2*p+1];
                float re = xe * c - xo * s;
                float ro = xe * s + xo * c;
                size_t base = ((size_t)(b*CH + h) * CT + t) * CDK + d;
                out[base]     = re;
                out[base + 1] = ro;
            }
        } else {
            #pragma unroll
            for (int j = 0; j < 4; j++) {
                int e = n0 + tx*4 + j;
                int h = e >> 6, d = e & 63;
                out[((size_t)(b*CH + h) * CT + t) * CDK + d] = acc[i][j];
            }
        }
    }
}

// ---------------------------------------------------------------------------
// Flash attention, causal. One block = one (bh, 64-query tile).
// Q,K stored in smem transposed [d][t]; V natural [t][d]; P transposed [key][qrow].
// 256 threads, 4x4 micro-tiles; per-row softmax stats via half-warp shfl.
// ---------------------------------------------------------------------------
__global__ __launch_bounds__(256) void attn_kernel(
    const float* __restrict__ Qg, const float* __restrict__ Kg,
    const float* __restrict__ Vg, float* __restrict__ cat)
{
    __shared__ float Qs[64][64];  // [d][t], pre-scaled by 1/sqrt(dk)
    __shared__ float KP[64][64];  // K as [d][key], then reused as P [key][qrow]
    __shared__ float Vs[64][64];  // [key][d]

    int qb = blockIdx.x, bh = blockIdx.y;
    int tid = threadIdx.x;
    int tx = tid & 15, ty = tid >> 4;

    const float* qbase = Qg + ((size_t)bh * CT + qb * 64) * CDK;
    #pragma unroll
    for (int u = 0; u < 4; u++) {
        int slot = tid + u * 256;
        int r = slot >> 4, c4 = slot & 15;
        float4 v = *(const float4*)&qbase[r * 64 + c4 * 4];
        Qs[c4*4+0][r] = v.x * 0.125f;
        Qs[c4*4+1][r] = v.y * 0.125f;
        Qs[c4*4+2][r] = v.z * 0.125f;
        Qs[c4*4+3][r] = v.w * 0.125f;
    }

    float m[4], l[4], O[4][4];
    #pragma unroll
    for (int i = 0; i < 4; i++) {
        m[i] = -1e30f; l[i] = 0.0f;
        #pragma unroll
        for (int j = 0; j < 4; j++) O[i][j] = 0.0f;
    }

    for (int kb = 0; kb <= qb; kb++) {
        const float* kbase = Kg + ((size_t)bh * CT + kb * 64) * CDK;
        const float* vbase = Vg + ((size_t)bh * CT + kb * 64) * CDK;
        #pragma unroll
        for (int u = 0; u < 4; u++) {
            int slot = tid + u * 256;
            int r = slot >> 4, c4 = slot & 15;
            float4 kv = *(const float4*)&kbase[r * 64 + c4 * 4];
            KP[c4*4+0][r] = kv.x; KP[c4*4+1][r] = kv.y;
            KP[c4*4+2][r] = kv.z; KP[c4*4+3][r] = kv.w;
            float4 vv = *(const float4*)&vbase[r * 64 + c4 * 4];
            *(float4*)&Vs[r][c4*4] = vv;
        }
        __syncthreads();

        // S = Qs^T * K  (dot over d)
        float S[4][4] = {};
        #pragma unroll 8
        for (int kk = 0; kk < 64; kk++) {
            float4 a = *(const float4*)&Qs[kk][ty*4];
            float4 b = *(const float4*)&KP[kk][tx*4];
            float ar[4] = {a.x, a.y, a.z, a.w};
            float br[4] = {b.x, b.y, b.z, b.w};
            #pragma unroll
            for (int i = 0; i < 4; i++)
                #pragma unroll
                for (int j = 0; j < 4; j++)
                    S[i][j] += ar[i] * br[j];
        }

        if (kb == qb) {
            #pragma unroll
            for (int i = 0; i < 4; i++)
                #pragma unroll
                for (int j = 0; j < 4; j++)
                    if (tx*4 + j > ty*4 + i) S[i][j] = -1e30f;
        }

        // Online softmax update; row is shared by a 16-lane half-warp (same ty).
        #pragma unroll
        for (int i = 0; i < 4; i++) {
            float mi = fmaxf(fmaxf(S[i][0], S[i][1]), fmaxf(S[i][2], S[i][3]));
            #pragma unroll
            for (int o = 8; o > 0; o >>= 1)
                mi = fmaxf(mi, __shfl_xor_sync(0xffffffffu, mi, o, 16));
            float mn = fmaxf(m[i], mi);
            float sc = __expf(m[i] - mn);
            float rs = 0.0f;
            #pragma unroll
            for (int j = 0; j < 4; j++) {
                S[i][j] = __expf(S[i][j] - mn);
                rs += S[i][j];
            }
            #pragma unroll
            for (int o = 8; o > 0; o >>= 1)
                rs += __shfl_xor_sync(0xffffffffu, rs, o, 16);
            l[i] = l[i] * sc + rs;
            m[i] = mn;
            #pragma unroll
            for (int j = 0; j < 4; j++) O[i][j] *= sc;
        }
        __syncthreads();  // everyone done reading KP as K

        // Store P transposed: KP[key][qrow]
        #pragma unroll
        for (int i = 0; i < 4; i++)
            #pragma unroll
            for (int j = 0; j < 4; j++)
                KP[tx*4 + j][ty*4 + i] = S[i][j];
        __syncthreads();

        // O += P * V  (dot over key)
        #pragma unroll 8
        for (int kk = 0; kk < 64; kk++) {
            float4 p = *(const float4*)&KP[kk][ty*4];
            float4 v = *(const float4*)&Vs[kk][tx*4];
            float pr[4] = {p.x, p.y, p.z, p.w};
            float vr[4] = {v.x, v.y, v.z, v.w};
            #pragma unroll
            for (int i = 0; i < 4; i++)
                #pragma unroll
                for (int j = 0; j < 4; j++)
                    O[i][j] += pr[i] * vr[j];
        }
        __syncthreads();  // before next iteration's loads overwrite KP/Vs
    }

    int b = bh >> 4, h = bh & 15;
    #pragma unroll
    for (int i = 0; i < 4; i++) {
        int t = qb * 64 + ty*4 + i;
        float inv = 1.0f / l[i];
        float4 o = make_float4(O[i][0]*inv, O[i][1]*inv, O[i][2]*inv, O[i][3]*inv);
        *(float4*)&cat[((size_t)(b * CT + t)) * CD + h * 64 + tx*4] = o;
    }
}

extern "C" void kernel_launch(void* const* d_in, const int* in_sizes, int n_in,
                              void* d_out, int out_size) {
    const float* x  = (const float*)d_in[0];
    const float* wq = (const float*)d_in[1];
    const float* wk = (const float*)d_in[2];
    const float* wv = (const float*)d_in[3];
    const float* wo = (const float*)d_in[4];
    float* out = (float*)d_out;

    float *q, *k, *v, *cat;
    cudaGetSymbolAddress((void**)&q,   g_q);
    cudaGetSymbolAddress((void**)&k,   g_k);
    cudaGetSymbolAddress((void**)&v,   g_v);
    cudaGetSymbolAddress((void**)&cat, g_cat);

    dim3 gg(CD / 64, CM / 64);   // (16, 64)
    gemm_proj<<<gg, 256>>>(x, wq, q, 1);   // Q proj + RoPE -> [B,H,T,dk]
    gemm_proj<<<gg, 256>>>(x, wk, k, 1);   // K proj + RoPE
    gemm_proj<<<gg, 256>>>(x, wv, v, 2);   // V proj

    dim3 ga(CT / 64, CB * CH);   // (32, 32)
    attn_kernel<<<ga, 256>>>(q, k, v, cat);

    gemm_proj<<<gg, 256>>>(cat, wo, out, 0);  // output projection
}

// round 4
// speedup vs baseline: 1.4392x; 1.4392x over previous
#include <cuda_runtime.h>
#include <math.h>
#include <stdint.h>

#define CB 2
#define CT 2048
#define CD 1024
#define CH 16
#define CDK 64
#define CM (CB*CT)   // 4096

// ---- mma.sync GEMM tiling ----
#define BM 128
#define BN 128
#define BK 32
#define NITER (CD/BK)   // 32

// Scratch (device globals: no allocation allowed)
__device__ float g_q[CB*CH*CT*CDK];
__device__ float g_k[CB*CH*CT*CDK];
__device__ float g_v[CB*CH*CT*CDK];
__device__ float g_cat[CM*CD];
__device__ float g_xr[CM*CD];        // x rounded to tf32
__device__ float g_wr[4][CD*CD];     // wq,wk,wv,wo rounded to tf32

__device__ __forceinline__ float rna_tf32(float x) {
    uint32_t r;
    asm("cvt.rna.tf32.f32 %0, %1;" : "=r"(r) : "f"(x));
    return __uint_as_float(r);
}

// ---------------------------------------------------------------------------
// Prepass: round fp32 -> nearest tf32 (zero-mean error for tensor-core GEMMs)
// ---------------------------------------------------------------------------
__global__ __launch_bounds__(256) void round_tf32_kernel(const float4* __restrict__ in,
                                                         float4* __restrict__ out, int n4) {
    int i = blockIdx.x * 256 + threadIdx.x;
    if (i < n4) {
        float4 v = in[i];
        v.x = rna_tf32(v.x); v.y = rna_tf32(v.y);
        v.z = rna_tf32(v.z); v.w = rna_tf32(v.w);
        out[i] = v;
    }
}

// ---------------------------------------------------------------------------
// mma.sync tf32 GEMM:  C[m,n] = sum_k A[m,k] * W[n,k]  (both K-contiguous)
// 256 threads = 8 warps (2x4); warp tile 64x32; m16n8k8 fragments.
// Smem holds tiles PRE-PERMUTED into fragment order:
//   A frag (fm,fk): 32 lanes x 4 floats  -> lane reads LDS.128, conflict-free
//   B frag (fn,fk): 32 lanes x 2 floats  -> lane reads LDS.64,  conflict-free
// mode 0: row-major [M,N]   mode 1: RoPE -> [B,H,T,dk]   mode 2: -> [B,H,T,dk]
// ---------------------------------------------------------------------------
__global__ __launch_bounds__(256) void gemm_mma(
    const float* __restrict__ A, const float* __restrict__ W,
    float* __restrict__ out, int mode)
{
    __shared__ float As[4096];   // 8 fm x 4 fk x 32 lanes x 4
    __shared__ float Bs[4096];   // 16 fn x 4 fk x 32 lanes x 2

    const int tid = threadIdx.x;
    const int wid = tid >> 5, lane = tid & 31;
    const int wr = wid >> 2, wc = wid & 3;       // warp grid 2 x 4
    const int m0 = blockIdx.y * BM, n0 = blockIdx.x * BN;

    float4 aPre[4], bPre[4];

    auto ldg = [&](int kt) {
        const float* ga = A + (size_t)m0 * CD + kt * BK;
        const float* gb = W + (size_t)n0 * CD + kt * BK;
        #pragma unroll
        for (int u = 0; u < 4; u++) {
            int idx = tid + u * 256;
            int r = idx >> 3, c4 = idx & 7;
            aPre[u] = *(const float4*)(ga + (size_t)r * CD + c4 * 4);
            bPre[u] = *(const float4*)(gb + (size_t)r * CD + c4 * 4);
        }
    };
    auto sts = [&]() {
        #pragma unroll
        for (int u = 0; u < 4; u++) {
            int idx = tid + u * 256;
            int r = idx >> 3, c4 = idx & 7;
            float av[4] = {aPre[u].x, aPre[u].y, aPre[u].z, aPre[u].w};
            float bv[4] = {bPre[u].x, bPre[u].y, bPre[u].z, bPre[u].w};
            #pragma unroll
            for (int e = 0; e < 4; e++) {
                int k = c4 * 4 + e;
                int fk = k >> 3, ki = k & 7;
                {   // A: a0: m=t/4,k=t%4 | a1: m=t/4+8 | a2: k=t%4+4 | a3: both
                    int fm = r >> 4, mi = r & 15;
                    int l = (mi & 7) * 4 + (ki & 3);
                    int slot = ((ki & 4) >> 1) | (mi >> 3);
                    As[((fm * 4 + fk) * 32 + l) * 4 + slot] = av[e];
                }
                {   // B: b0: k=t%4,n=t/4 | b1: k=t%4+4
                    int fn = r >> 3, ni = r & 7;
                    int l = ni * 4 + (ki & 3);
                    int slot = ki >> 2;
                    Bs[((fn * 4 + fk) * 32 + l) * 2 + slot] = bv[e];
                }
            }
        }
    };

    float acc[4][4][4] = {};

    ldg(0); sts();
    __syncthreads();

    for (int kt = 0; kt < NITER; kt++) {
        if (kt + 1 < NITER) ldg(kt + 1);
        #pragma unroll
        for (int fk = 0; fk < 4; fk++) {
            uint32_t a[4][4], b[4][2];
            #pragma unroll
            for (int am = 0; am < 4; am++) {
                int fm = wr * 4 + am;
                uint4 t = *(const uint4*)&As[((fm * 4 + fk) * 32 + lane) * 4];
                a[am][0] = t.x; a[am][1] = t.y; a[am][2] = t.z; a[am][3] = t.w;
            }
            #pragma unroll
            for (int bn = 0; bn < 4; bn++) {
                int fn = wc * 4 + bn;
                uint2 t = *(const uint2*)&Bs[((fn * 4 + fk) * 32 + lane) * 2];
                b[bn][0] = t.x; b[bn][1] = t.y;
            }
            #pragma unroll
            for (int am = 0; am < 4; am++)
                #pragma unroll
                for (int bn = 0; bn < 4; bn++)
                    asm volatile(
                        "mma.sync.aligned.m16n8k8.row.col.f32.tf32.tf32.f32 "
                        "{%0,%1,%2,%3}, {%4,%5,%6,%7}, {%8,%9}, {%0,%1,%2,%3};"
                        : "+f"(acc[am][bn][0]), "+f"(acc[am][bn][1]),
                          "+f"(acc[am][bn][2]), "+f"(acc[am][bn][3])
                        : "r"(a[am][0]), "r"(a[am][1]), "r"(a[am][2]), "r"(a[am][3]),
                          "r"(b[bn][0]), "r"(b[bn][1]));
        }
        __syncthreads();
        if (kt + 1 < NITER) { sts(); __syncthreads(); }
    }

    // ---- epilogue: acc layout: rows t/4 (c0,c1) and t/4+8 (c2,c3); cols 2*(t%4)+{0,1}
    const int qrow = lane >> 2, qcol = (lane & 3) * 2;
    #pragma unroll
    for (int am = 0; am < 4; am++) {
        #pragma unroll
        for (int half = 0; half < 2; half++) {
            int m = m0 + (wr * 4 + am) * 16 + qrow + half * 8;
            int b_ = m >> 11, t = m & (CT - 1);
            #pragma unroll
            for (int bn = 0; bn < 4; bn++) {
                int col = n0 + (wc * 4 + bn) * 8 + qcol;
                float v0 = acc[am][bn][half * 2 + 0];
                float v1 = acc[am][bn][half * 2 + 1];
                if (mode == 0) {
                    *(float2*)&out[(size_t)m * CD + col] = make_float2(v0, v1);
                } else {
                    int h = col >> 6, d = col & 63;
                    if (mode == 1) {
                        int pidx = d >> 1;
                        float inv = exp2f(-(float)pidx * (9.965784284662087f / 32.0f));
                        float sn, cs;
                        sincosf((float)t * inv, &sn, &cs);
                        float re = v0 * cs - v1 * sn;
                        float ro = v0 * sn + v1 * cs;
                        *(float2*)&out[(((size_t)(b_ * CH + h) * CT + t) << 6) + d] =
                            make_float2(re, ro);
                    } else {
                        *(float2*)&out[(((size_t)(b_ * CH + h) * CT + t) << 6) + d] =
                            make_float2(v0, v1);
                    }
                }
            }
        }
    }
}

// ---------------------------------------------------------------------------
// Flash attention, causal (fp32; cat outputs pre-rounded to tf32 for out-proj)
// ---------------------------------------------------------------------------
__global__ __launch_bounds__(256) void attn_kernel(
    const float* __restrict__ Qg, const float* __restrict__ Kg,
    const float* __restrict__ Vg, float* __restrict__ cat)
{
    __shared__ float Qs[64][64];
    __shared__ float KP[64][64];
    __shared__ float Vs[64][64];

    int qb = blockIdx.x, bh = blockIdx.y;
    int tid = threadIdx.x;
    int tx = tid & 15, ty = tid >> 4;

    const float* qbase = Qg + ((size_t)bh * CT + qb * 64) * CDK;
    #pragma unroll
    for (int u = 0; u < 4; u++) {
        int slot = tid + u * 256;
        int r = slot >> 4, c4 = slot & 15;
        float4 v = *(const float4*)&qbase[r * 64 + c4 * 4];
        Qs[c4*4+0][r] = v.x * 0.125f;
        Qs[c4*4+1][r] = v.y * 0.125f;
        Qs[c4*4+2][r] = v.z * 0.125f;
        Qs[c4*4+3][r] = v.w * 0.125f;
    }

    float m[4], l[4], O[4][4];
    #pragma unroll
    for (int i = 0; i < 4; i++) {
        m[i] = -1e30f; l[i] = 0.0f;
        #pragma unroll
        for (int j = 0; j < 4; j++) O[i][j] = 0.0f;
    }

    for (int kb = 0; kb <= qb; kb++) {
        const float* kbase = Kg + ((size_t)bh * CT + kb * 64) * CDK;
        const float* vbase = Vg + ((size_t)bh * CT + kb * 64) * CDK;
        #pragma unroll
        for (int u = 0; u < 4; u++) {
            int slot = tid + u * 256;
            int r = slot >> 4, c4 = slot & 15;
            float4 kv = *(const float4*)&kbase[r * 64 + c4 * 4];
            KP[c4*4+0][r] = kv.x; KP[c4*4+1][r] = kv.y;
            KP[c4*4+2][r] = kv.z; KP[c4*4+3][r] = kv.w;
            float4 vv = *(const float4*)&vbase[r * 64 + c4 * 4];
            *(float4*)&Vs[r][c4*4] = vv;
        }
        __syncthreads();

        float S[4][4] = {};
        #pragma unroll 8
        for (int kk = 0; kk < 64; kk++) {
            float4 a = *(const float4*)&Qs[kk][ty*4];
            float4 bq = *(const float4*)&KP[kk][tx*4];
            float ar[4] = {a.x, a.y, a.z, a.w};
            float br[4] = {bq.x, bq.y, bq.z, bq.w};
            #pragma unroll
            for (int i = 0; i < 4; i++)
                #pragma unroll
                for (int j = 0; j < 4; j++)
                    S[i][j] += ar[i] * br[j];
        }

        if (kb == qb) {
            #pragma unroll
            for (int i = 0; i < 4; i++)
                #pragma unroll
                for (int j = 0; j < 4; j++)
                    if (tx*4 + j > ty*4 + i) S[i][j] = -1e30f;
        }

        #pragma unroll
        for (int i = 0; i < 4; i++) {
            float mi = fmaxf(fmaxf(S[i][0], S[i][1]), fmaxf(S[i][2], S[i][3]));
            #pragma unroll
            for (int o = 8; o > 0; o >>= 1)
                mi = fmaxf(mi, __shfl_xor_sync(0xffffffffu, mi, o, 16));
            float mn = fmaxf(m[i], mi);
            float sc = __expf(m[i] - mn);
            float rs = 0.0f;
            #pragma unroll
            for (int j = 0; j < 4; j++) {
                S[i][j] = __expf(S[i][j] - mn);
                rs += S[i][j];
            }
            #pragma unroll
            for (int o = 8; o > 0; o >>= 1)
                rs += __shfl_xor_sync(0xffffffffu, rs, o, 16);
            l[i] = l[i] * sc + rs;
            m[i] = mn;
            #pragma unroll
            for (int j = 0; j < 4; j++) O[i][j] *= sc;
        }
        __syncthreads();

        #pragma unroll
        for (int i = 0; i < 4; i++)
            #pragma unroll
            for (int j = 0; j < 4; j++)
                KP[tx*4 + j][ty*4 + i] = S[i][j];
        __syncthreads();

        #pragma unroll 8
        for (int kk = 0; kk < 64; kk++) {
            float4 p = *(const float4*)&KP[kk][ty*4];
            float4 v = *(const float4*)&Vs[kk][tx*4];
            float pr[4] = {p.x, p.y, p.z, p.w};
            float vr[4] = {v.x, v.y, v.z, v.w};
            #pragma unroll
            for (int i = 0; i < 4; i++)
                #pragma unroll
                for (int j = 0; j < 4; j++)
                    O[i][j] += pr[i] * vr[j];
        }
        __syncthreads();
    }

    int b = bh >> 4, h = bh & 15;
    #pragma unroll
    for (int i = 0; i < 4; i++) {
        int t = qb * 64 + ty*4 + i;
        float inv = 1.0f / l[i];
        float4 o = make_float4(rna_tf32(O[i][0]*inv), rna_tf32(O[i][1]*inv),
                               rna_tf32(O[i][2]*inv), rna_tf32(O[i][3]*inv));
        *(float4*)&cat[((size_t)(b * CT + t)) * CD + h * 64 + tx*4] = o;
    }
}

extern "C" void kernel_launch(void* const* d_in, const int* in_sizes, int n_in,
                              void* d_out, int out_size) {
    const float* x  = (const float*)d_in[0];
    const float* wq = (const float*)d_in[1];
    const float* wk = (const float*)d_in[2];
    const float* wv = (const float*)d_in[3];
    const float* wo = (const float*)d_in[4];
    float* out = (float*)d_out;

    float *q, *k, *v, *cat, *xr, *wr;
    cudaGetSymbolAddress((void**)&q,   g_q);
    cudaGetSymbolAddress((void**)&k,   g_k);
    cudaGetSymbolAddress((void**)&v,   g_v);
    cudaGetSymbolAddress((void**)&cat, g_cat);
    cudaGetSymbolAddress((void**)&xr,  g_xr);
    cudaGetSymbolAddress((void**)&wr,  g_wr);

    // prepass: round all GEMM inputs to nearest tf32
    const int n4x = CM * CD / 4;
    const int n4w = CD * CD / 4;
    round_tf32_kernel<<<n4x / 256, 256>>>((const float4*)x,  (float4*)xr, n4x);
    round_tf32_kernel<<<n4w / 256, 256>>>((const float4*)wq, (float4*)(wr + 0*CD*CD), n4w);
    round_tf32_kernel<<<n4w / 256, 256>>>((const float4*)wk, (float4*)(wr + 1*CD*CD), n4w);
    round_tf32_kernel<<<n4w / 256, 256>>>((const float4*)wv, (float4*)(wr + 2*CD*CD), n4w);
    round_tf32_kernel<<<n4w / 256, 256>>>((const float4*)wo, (float4*)(wr + 3*CD*CD), n4w);

    dim3 gg(CD / BN, CM / BM);   // (8, 32)
    gemm_mma<<<gg, 256>>>(xr, wr + 0*CD*CD, q, 1);   // Q proj + RoPE
    gemm_mma<<<gg, 256>>>(xr, wr + 1*CD*CD, k, 1);   // K proj + RoPE
    gemm_mma<<<gg, 256>>>(xr, wr + 2*CD*CD, v, 2);   // V proj

    dim3 ga(CT / 64, CB * CH);   // (32, 32)
    attn_kernel<<<ga, 256>>>(q, k, v, cat);

    gemm_mma<<<gg, 256>>>(cat, wr + 3*CD*CD, out, 0); // output proj
}

// round 7
// speedup vs baseline: 2.3124x; 1.6068x over previous
#include <cuda_runtime.h>
#include <math.h>
#include <stdint.h>

#define CB 2
#define CT 2048
#define CD 1024
#define CH 16
#define CDK 64
#define CM (CB*CT)   // 4096

// ---- mma.sync GEMM tiling ----
#define BM 128
#define BN 128
#define BK 32
#define NITER (CD/BK)   // 32

// Scratch (device globals: no allocation allowed)
__device__ float g_q[CB*CH*CT*CDK];
__device__ float g_k[CB*CH*CT*CDK];
__device__ float g_v[CB*CH*CT*CDK];
__device__ float g_cat[CM*CD];
__device__ float g_xr[CM*CD];        // x rounded to tf32
__device__ float g_wr[4][CD*CD];     // wq,wk,wv,wo rounded to tf32

__device__ __forceinline__ float rna_tf32(float x) {
    uint32_t r;
    asm("cvt.rna.tf32.f32 %0, %1;" : "=r"(r) : "f"(x));
    return __uint_as_float(r);
}

__device__ __forceinline__ void mma8(float c[4], const uint32_t a[4],
                                     uint32_t b0, uint32_t b1) {
    asm volatile(
        "mma.sync.aligned.m16n8k8.row.col.f32.tf32.tf32.f32 "
        "{%0,%1,%2,%3}, {%4,%5,%6,%7}, {%8,%9}, {%0,%1,%2,%3};"
        : "+f"(c[0]), "+f"(c[1]), "+f"(c[2]), "+f"(c[3])
        : "r"(a[0]), "r"(a[1]), "r"(a[2]), "r"(a[3]), "r"(b0), "r"(b1));
}

// ---------------------------------------------------------------------------
// Prepass: round fp32 -> nearest tf32 (zero-mean error for tensor-core GEMMs)
// ---------------------------------------------------------------------------
__global__ __launch_bounds__(256) void round_tf32_kernel(const float4* __restrict__ in,
                                                         float4* __restrict__ out, int n4) {
    int i = blockIdx.x * 256 + threadIdx.x;
    if (i < n4) {
        float4 v = in[i];
        v.x = rna_tf32(v.x); v.y = rna_tf32(v.y);
        v.z = rna_tf32(v.z); v.w = rna_tf32(v.w);
        out[i] = v;
    }
}

// ---------------------------------------------------------------------------
// mma.sync tf32 GEMM:  C[m,n] = sum_k A[m,k] * W[n,k]  (both K-contiguous)
// mode 0: row-major [M,N] (fp32, unrounded)
// mode 1: RoPE -> [B,H,T,dk], rna-tf32 rounded
// mode 2: -> [B,H,T,dk], rna-tf32 rounded
// ---------------------------------------------------------------------------
__global__ __launch_bounds__(256) void gemm_mma(
    const float* __restrict__ A, const float* __restrict__ W,
    float* __restrict__ out, int mode)
{
    __shared__ float As[4096];   // 8 fm x 4 fk x 32 lanes x 4
    __shared__ float Bs[4096];   // 16 fn x 4 fk x 32 lanes x 2

    const int tid = threadIdx.x;
    const int wid = tid >> 5, lane = tid & 31;
    const int wr = wid >> 2, wc = wid & 3;       // warp grid 2 x 4
    const int m0 = blockIdx.y * BM, n0 = blockIdx.x * BN;

    float4 aPre[4], bPre[4];

    auto ldg = [&](int kt) {
        const float* ga = A + (size_t)m0 * CD + kt * BK;
        const float* gb = W + (size_t)n0 * CD + kt * BK;
        #pragma unroll
        for (int u = 0; u < 4; u++) {
            int idx = tid + u * 256;
            int r = idx >> 3, c4 = idx & 7;
            aPre[u] = *(const float4*)(ga + (size_t)r * CD + c4 * 4);
            bPre[u] = *(const float4*)(gb + (size_t)r * CD + c4 * 4);
        }
    };
    auto sts = [&]() {
        #pragma unroll
        for (int u = 0; u < 4; u++) {
            int idx = tid + u * 256;
            int r = idx >> 3, c4 = idx & 7;
            float av[4] = {aPre[u].x, aPre[u].y, aPre[u].z, aPre[u].w};
            float bv[4] = {bPre[u].x, bPre[u].y, bPre[u].z, bPre[u].w};
            #pragma unroll
            for (int e = 0; e < 4; e++) {
                int k = c4 * 4 + e;
                int fk = k >> 3, ki = k & 7;
                {
                    int fm = r >> 4, mi = r & 15;
                    int l = (mi & 7) * 4 + (ki & 3);
                    int slot = ((ki & 4) >> 1) | (mi >> 3);
                    As[((fm * 4 + fk) * 32 + l) * 4 + slot] = av[e];
                }
                {
                    int fn = r >> 3, ni = r & 7;
                    int l = ni * 4 + (ki & 3);
                    int slot = ki >> 2;
                    Bs[((fn * 4 + fk) * 32 + l) * 2 + slot] = bv[e];
                }
            }
        }
    };

    float acc[4][4][4] = {};

    ldg(0); sts();
    __syncthreads();

    for (int kt = 0; kt < NITER; kt++) {
        if (kt + 1 < NITER) ldg(kt + 1);
        #pragma unroll
        for (int fk = 0; fk < 4; fk++) {
            uint32_t a[4][4], b[4][2];
            #pragma unroll
            for (int am = 0; am < 4; am++) {
                int fm = wr * 4 + am;
                uint4 t = *(const uint4*)&As[((fm * 4 + fk) * 32 + lane) * 4];
                a[am][0] = t.x; a[am][1] = t.y; a[am][2] = t.z; a[am][3] = t.w;
            }
            #pragma unroll
            for (int bn = 0; bn < 4; bn++) {
                int fn = wc * 4 + bn;
                uint2 t = *(const uint2*)&Bs[((fn * 4 + fk) * 32 + lane) * 2];
                b[bn][0] = t.x; b[bn][1] = t.y;
            }
            #pragma unroll
            for (int am = 0; am < 4; am++)
                #pragma unroll
                for (int bn = 0; bn < 4; bn++)
                    mma8(acc[am][bn], a[am], b[bn][0], b[bn][1]);
        }
        __syncthreads();
        if (kt + 1 < NITER) { sts(); __syncthreads(); }
    }

    const int qrow = lane >> 2, qcol = (lane & 3) * 2;
    #pragma unroll
    for (int am = 0; am < 4; am++) {
        #pragma unroll
        for (int half = 0; half < 2; half++) {
            int m = m0 + (wr * 4 + am) * 16 + qrow + half * 8;
            int b_ = m >> 11, t = m & (CT - 1);
            #pragma unroll
            for (int bn = 0; bn < 4; bn++) {
                int col = n0 + (wc * 4 + bn) * 8 + qcol;
                float v0 = acc[am][bn][half * 2 + 0];
                float v1 = acc[am][bn][half * 2 + 1];
                if (mode == 0) {
                    *(float2*)&out[(size_t)m * CD + col] = make_float2(v0, v1);
                } else {
                    int h = col >> 6, d = col & 63;
                    if (mode == 1) {
                        int pidx = d >> 1;
                        float inv = exp2f(-(float)pidx * (9.965784284662087f / 32.0f));
                        float sn, cs;
                        sincosf((float)t * inv, &sn, &cs);
                        float re = v0 * cs - v1 * sn;
                        float ro = v0 * sn + v1 * cs;
                        *(float2*)&out[(((size_t)(b_ * CH + h) * CT + t) << 6) + d] =
                            make_float2(rna_tf32(re), rna_tf32(ro));
                    } else {
                        *(float2*)&out[(((size_t)(b_ * CH + h) * CT + t) << 6) + d] =
                            make_float2(rna_tf32(v0), rna_tf32(v1));
                    }
                }
            }
        }
    }
}

// ---------------------------------------------------------------------------
// Flash attention, causal, tf32 mma.sync.
// 128 threads = 4 warps; warp w owns queries [16w,16w+16) of a 64-query tile.
// Q as A-frags in regs; K/V tiles permuted to fragment order in smem;
// softmax on mma accumulator layout; P->A-frag via register shuffles.
// ---------------------------------------------------------------------------
__global__ __launch_bounds__(128) void attn_mma(
    const float* __restrict__ Qg, const float* __restrict__ Kg,
    const float* __restrict__ Vg, float* __restrict__ cat)
{
    __shared__ float Qs[4096];   // [mf4][kf8][lane][4]
    __shared__ float Ks[4096];   // [kf8(d)][nf8(key)][lane][2]
    __shared__ float Vs[4096];   // [kf8(key)][nf8(d)][lane][2]

    const int qb = blockIdx.x, bh = blockIdx.y;
    const int tid = threadIdx.x, wid = tid >> 5, lane = tid & 31;

    // ---- stage Q (scaled by 1/8) permuted, then pull A-frags into regs
    const float* qbase = Qg + ((size_t)bh * CT + qb * 64) * CDK;
    #pragma unroll
    for (int u = 0; u < 8; u++) {
        int idx = tid + u * 128;
        int r = idx >> 4, c4 = idx & 15;
        float4 v = *(const float4*)&qbase[r * 64 + c4 * 4];
        float vv[4] = {v.x, v.y, v.z, v.w};
        int mf = r >> 4, mi = r & 15;
        #pragma unroll
        for (int e = 0; e < 4; e++) {
            int c = c4 * 4 + e;
            int kf = c >> 3, ki = c & 7;
            int l = (mi & 7) * 4 + (ki & 3);
            int slot = ((ki & 4) >> 1) | (mi >> 3);
            Qs[((mf * 8 + kf) * 32 + l) * 4 + slot] = vv[e] * 0.125f;
        }
    }
    __syncthreads();
    uint32_t qa[8][4];
    #pragma unroll
    for (int kf = 0; kf < 8; kf++) {
        uint4 t = *(const uint4*)&Qs[((wid * 8 + kf) * 32 + lane) * 4];
        qa[kf][0] = t.x; qa[kf][1] = t.y; qa[kf][2] = t.z; qa[kf][3] = t.w;
    }
    __syncthreads();   // Qs no longer needed

    float m_[2] = {-1e30f, -1e30f}, l_[2] = {0.0f, 0.0f};
    float O[8][4] = {};

    const int src0 = (lane & ~3) | ((lane & 3) >> 1);
    const int src2 = src0 | 2;
    const bool sel = lane & 1;
    const int row0 = wid * 16 + (lane >> 2);

    for (int kb = 0; kb <= qb; kb++) {
        const float* kbase = Kg + ((size_t)bh * CT + kb * 64) * CDK;
        const float* vbase = Vg + ((size_t)bh * CT + kb * 64) * CDK;
        #pragma unroll
        for (int u = 0; u < 8; u++) {
            int idx = tid + u * 128;
            int r = idx >> 4, c4 = idx & 15;
            float4 kv = *(const float4*)&kbase[r * 64 + c4 * 4];
            float4 vv = *(const float4*)&vbase[r * 64 + c4 * 4];
            float ka[4] = {kv.x, kv.y, kv.z, kv.w};
            float va[4] = {vv.x, vv.y, vv.z, vv.w};
            int nfK = r >> 3, niK = r & 7;          // K: key -> n
            int kfV = r >> 3, kiV = r & 7;          // V: key -> k
            #pragma unroll
            for (int e = 0; e < 4; e++) {
                int c = c4 * 4 + e;
                // K frag: [kf=c>>3][nf=nfK] lane=niK*4+(c&3) slot=(c&7)>>2
                Ks[(((c >> 3) * 8 + nfK) * 32 + niK * 4 + (c & 3)) * 2 + ((c & 7) >> 2)] = ka[e];
                // V frag: [kf=kfV][nf=c>>3] lane=(c&7)*4+(kiV&3) slot=(kiV)>>2
                Vs[((kfV * 8 + (c >> 3)) * 32 + (c & 7) * 4 + (kiV & 3)) * 2 + (kiV >> 2)] = va[e];
            }
        }
        __syncthreads();

        // ---- S = Q K^T
        float S[8][4] = {};
        #pragma unroll
        for (int kf = 0; kf < 8; kf++) {
            #pragma unroll
            for (int nf = 0; nf < 8; nf++) {
                uint2 kfr = *(const uint2*)&Ks[((kf * 8 + nf) * 32 + lane) * 2];
                mma8(S[nf], qa[kf], kfr.x, kfr.y);
            }
        }

        if (kb == qb) {
            #pragma unroll
            for (int nf = 0; nf < 8; nf++)
                #pragma unroll
                for (int e = 0; e < 4; e++) {
                    int col = nf * 8 + 2 * (lane & 3) + (e & 1);
                    int row = row0 + ((e >> 1) << 3);
                    if (col > row) S[nf][e] = -1e30f;
                }
        }

        // ---- online softmax on accumulator layout (quad-lane reductions)
        #pragma unroll
        for (int h = 0; h < 2; h++) {
            float mx = -1e30f;
            #pragma unroll
            for (int nf = 0; nf < 8; nf++)
                mx = fmaxf(mx, fmaxf(S[nf][2*h], S[nf][2*h + 1]));
            mx = fmaxf(mx, __shfl_xor_sync(0xffffffffu, mx, 1));
            mx = fmaxf(mx, __shfl_xor_sync(0xffffffffu, mx, 2));
            float mn = fmaxf(m_[h], mx);
            float sc = __expf(m_[h] - mn);
            float rs = 0.0f;
            #pragma unroll
            for (int nf = 0; nf < 8; nf++) {
                float p0 = rna_tf32(__expf(S[nf][2*h]     - mn));
                float p1 = rna_tf32(__expf(S[nf][2*h + 1] - mn));
                S[nf][2*h] = p0; S[nf][2*h + 1] = p1;
                rs += p0 + p1;
            }
            rs += __shfl_xor_sync(0xffffffffu, rs, 1);
            rs += __shfl_xor_sync(0xffffffffu, rs, 2);
            l_[h] = l_[h] * sc + rs;
            m_[h] = mn;
            #pragma unroll
            for (int nf = 0; nf < 8; nf++) { O[nf][2*h] *= sc; O[nf][2*h + 1] *= sc; }
        }

        // ---- O += P V  (P: C-layout -> A-frag via shfl; no smem, no sync)
        #pragma unroll
        for (int j = 0; j < 8; j++) {
            float t00 = __shfl_sync(0xffffffffu, S[j][0], src0);
            float t01 = __shfl_sync(0xffffffffu, S[j][1], src0);
            float t20 = __shfl_sync(0xffffffffu, S[j][0], src2);
            float t21 = __shfl_sync(0xffffffffu, S[j][1], src2);
            float t10 = __shfl_sync(0xffffffffu, S[j][2], src0);
            float t11 = __shfl_sync(0xffffffffu, S[j][3], src0);
            float t30 = __shfl_sync(0xffffffffu, S[j][2], src2);
            float t31 = __shfl_sync(0xffffffffu, S[j][3], src2);
            uint32_t pa[4];
            pa[0] = __float_as_uint(sel ? t01 : t00);
            pa[1] = __float_as_uint(sel ? t11 : t10);
            pa[2] = __float_as_uint(sel ? t21 : t20);
            pa[3] = __float_as_uint(sel ? t31 : t30);
            #pragma unroll
            for (int nf = 0; nf < 8; nf++) {
                uint2 vf = *(const uint2*)&Vs[((j * 8 + nf) * 32 + lane) * 2];
                mma8(O[nf], pa, vf.x, vf.y);
            }
        }
        __syncthreads();   // before next tile overwrites Ks/Vs
    }

    // ---- epilogue: normalize, rna-round (feeds the out-proj tf32 GEMM)
    const int b = bh >> 4, h = bh & 15;
    #pragma unroll
    for (int h2 = 0; h2 < 2; h2++) {
        int t = qb * 64 + wid * 16 + (lane >> 2) + h2 * 8;
        float inv = 1.0f / l_[h2];
        #pragma unroll
        for (int nf = 0; nf < 8; nf++) {
            int d = nf * 8 + 2 * (lane & 3);
            float2 o = make_float2(rna_tf32(O[nf][2*h2] * inv),
                                   rna_tf32(O[nf][2*h2 + 1] * inv));
            *(float2*)&cat[((size_t)(b * CT + t)) * CD + h * 64 + d] = o;
        }
    }
}

extern "C" void kernel_launch(void* const* d_in, const int* in_sizes, int n_in,
                              void* d_out, int out_size) {
    const float* x  = (const float*)d_in[0];
    const float* wq = (const float*)d_in[1];
    const float* wk = (const float*)d_in[2];
    const float* wv = (const float*)d_in[3];
    const float* wo = (const float*)d_in[4];
    float* out = (float*)d_out;

    float *q, *k, *v, *cat, *xr, *wr;
    cudaGetSymbolAddress((void**)&q,   g_q);
    cudaGetSymbolAddress((void**)&k,   g_k);
    cudaGetSymbolAddress((void**)&v,   g_v);
    cudaGetSymbolAddress((void**)&cat, g_cat);
    cudaGetSymbolAddress((void**)&xr,  g_xr);
    cudaGetSymbolAddress((void**)&wr,  g_wr);

    const int n4x = CM * CD / 4;
    const int n4w = CD * CD / 4;
    round_tf32_kernel<<<n4x / 256, 256>>>((const float4*)x,  (float4*)xr, n4x);
    round_tf32_kernel<<<n4w / 256, 256>>>((const float4*)wq, (float4*)(wr + 0*CD*CD), n4w);
    round_tf32_kernel<<<n4w / 256, 256>>>((const float4*)wk, (float4*)(wr + 1*CD*CD), n4w);
    round_tf32_kernel<<<n4w / 256, 256>>>((const float4*)wv, (float4*)(wr + 2*CD*CD), n4w);
    round_tf32_kernel<<<n4w / 256, 256>>>((const float4*)wo, (float4*)(wr + 3*CD*CD), n4w);

    dim3 gg(CD / BN, CM / BM);   // (8, 32)
    gemm_mma<<<gg, 256>>>(xr, wr + 0*CD*CD, q, 1);   // Q proj + RoPE (tf32-rounded)
    gemm_mma<<<gg, 256>>>(xr, wr + 1*CD*CD, k, 1);   // K proj + RoPE (tf32-rounded)
    gemm_mma<<<gg, 256>>>(xr, wr + 2*CD*CD, v, 2);   // V proj (tf32-rounded)

    dim3 ga(CT / 64, CB * CH);   // (32, 32)
    attn_mma<<<ga, 128>>>(q, k, v, cat);

    gemm_mma<<<gg, 256>>>(cat, wr + 3*CD*CD, out, 0); // output proj (fp32 out)
}

// round 8
// speedup vs baseline: 4.9548x; 2.1427x over previous
#include <cuda_runtime.h>
#include <math.h>
#include <stdint.h>

#define CB 2
#define CT 2048
#define CD 1024
#define CH 16
#define CM (CB*CT)   // 4096

#define BM 128
#define BN 128
#define BK 32
#define NITER (CD/BK)   // 32
#define NSTG 3
#define A_STG_B 16384
#define B_STG_B 16384
#define STG_B (A_STG_B + B_STG_B)          // 32768
#define GEMM_SMEM (NSTG*STG_B)             // 98304
#define ATTN_SMEM (2*32768)                // 65536

// Scratch (device globals; all in fragment order)
__device__ float g_xp[CM*CD];        // x as A-frags
__device__ float g_wp[4][CD*CD];     // wq,wk,wv,wo as B-frags
__device__ float g_qp[CM*CD];        // Q A-frags per (bh,qb)
__device__ float g_kp[CM*CD];        // K B-frags per (bh,kb)
__device__ float g_vp[CM*CD];        // V B-frags per (bh,kb)
__device__ float g_catp[CM*CD];      // concat as A-frags

__device__ __forceinline__ float rna_tf32(float x) {
    uint32_t r;
    asm("cvt.rna.tf32.f32 %0, %1;" : "=r"(r) : "f"(x));
    return __uint_as_float(r);
}
__device__ __forceinline__ uint32_t smem_u32(const void* p) {
    uint32_t a;
    asm("{ .reg .u64 t; cvta.to.shared.u64 t, %1; cvt.u32.u64 %0, t; }" : "=r"(a) : "l"(p));
    return a;
}
__device__ __forceinline__ void cpasync16(uint32_t dst, const void* src) {
    asm volatile("cp.async.cg.shared.global [%0], [%1], 16;" :: "r"(dst), "l"(src));
}
#define CP_COMMIT() asm volatile("cp.async.commit_group;")
#define CP_WAIT(n)  asm volatile("cp.async.wait_group %0;" :: "n"(n))

__device__ __forceinline__ void mma8(float c[4], const uint32_t a[4],
                                     uint32_t b0, uint32_t b1) {
    asm volatile(
        "mma.sync.aligned.m16n8k8.row.col.f32.tf32.tf32.f32 "
        "{%0,%1,%2,%3}, {%4,%5,%6,%7}, {%8,%9}, {%0,%1,%2,%3};"
        : "+f"(c[0]), "+f"(c[1]), "+f"(c[2]), "+f"(c[3])
        : "r"(a[0]), "r"(a[1]), "r"(a[2]), "r"(a[3]), "r"(b0), "r"(b1));
}

// ---------------------------------------------------------------------------
// Prepass: fp32 -> tf32(rna) + permute into fragment order.
// A-frag: [mf][kf][lane][slot4]  lane=(mi&7)*4+(ki&3), slot=((ki&4)>>1)|(mi>>3)
// B-frag: [nf][kf][lane][slot2]  lane=ni*4+(ki&3),     slot=ki>>2
// ---------------------------------------------------------------------------
__global__ __launch_bounds__(256) void permA(const float* __restrict__ in,
                                             float* __restrict__ out) {
    int gid = blockIdx.x * 256 + threadIdx.x;      // (M/16)*(K/8)*32 threads
    int lane = gid & 31, frag = gid >> 5;
    int kf = frag & 127, mf = frag >> 7;
    int mi = lane >> 2, ki = lane & 3;
    const float* p = in + (size_t)(mf * 16 + mi) * CD + kf * 8 + ki;
    float4 v;
    v.x = rna_tf32(p[0]);
    v.y = rna_tf32(p[8 * CD]);
    v.z = rna_tf32(p[4]);
    v.w = rna_tf32(p[8 * CD + 4]);
    ((float4*)out)[gid] = v;
}
__global__ __launch_bounds__(256) void permB(const float* __restrict__ in,
                                             float* __restrict__ out) {
    int gid = blockIdx.x * 256 + threadIdx.x;      // (N/8)*(K/8)*32 threads
    int lane = gid & 31, frag = gid >> 5;
    int kf = frag & 127, nf = frag >> 7;
    int ni = lane >> 2, ki = lane & 3;
    const float* p = in + (size_t)(nf * 8 + ni) * CD + kf * 8 + ki;
    ((float2*)out)[gid] = make_float2(rna_tf32(p[0]), rna_tf32(p[4]));
}

// ---------------------------------------------------------------------------
// tf32 GEMM on pre-permuted fragments. cp.async 3-stage pipeline.
// C[m,n] = sum_k A[m,k]*W[n,k].  8 warps (2x4), warp tile 64x32.
// mode 0: row-major fp32 out
// mode 1: Q = RoPE -> Q-frags     mode 2: K = RoPE -> K-frags
// mode 3: V -> V-frags
// ---------------------------------------------------------------------------
__global__ __launch_bounds__(256) void gemm_f(
    const float* __restrict__ A, const float* __restrict__ W,
    float* __restrict__ out, int mode)
{
    extern __shared__ float sm[];
    const uint32_t sbase = smem_u32(sm);
    const int tid = threadIdx.x;
    const int wid = tid >> 5, lane = tid & 31;
    const int wr = wid >> 2, wc = wid & 3;
    const int m0 = blockIdx.y * BM, n0 = blockIdx.x * BN;

    auto issue = [&](int kt) {
        int st = kt % NSTG;
        uint32_t dA = sbase + st * STG_B;
        #pragma unroll
        for (int p = 0; p < 4; p++) {
            int idx = tid + p * 256;
            int fm = idx >> 7, inner = idx & 127;
            const float* s = A + ((size_t)(m0 / 16 + fm) * (CD / 8) + kt * 4) * 128 + inner * 4;
            cpasync16(dA + idx * 16, s);
        }
        uint32_t dB = dA + A_STG_B;
        #pragma unroll
        for (int p = 0; p < 4; p++) {
            int idx = tid + p * 256;
            int fn = idx >> 6, inner = idx & 63;
            const float* s = W + ((size_t)(n0 / 8 + fn) * (CD / 8) + kt * 4) * 64 + inner * 4;
            cpasync16(dB + idx * 16, s);
        }
    };

    issue(0); CP_COMMIT();
    issue(1); CP_COMMIT();
    issue(2); CP_COMMIT();

    float acc[4][4][4] = {};

    for (int kt = 0; kt < NITER; kt++) {
        const int st = kt % NSTG;
        const float* As = sm + st * (STG_B / 4);
        const float* Bs = As + (A_STG_B / 4);
        CP_WAIT(2);
        __syncthreads();
        #pragma unroll
        for (int fk = 0; fk < 4; fk++) {
            uint32_t a[4][4], b[4][2];
            #pragma unroll
            for (int am = 0; am < 4; am++) {
                uint4 t = *(const uint4*)&As[(((wr * 4 + am) * 4 + fk) * 32 + lane) * 4];
                a[am][0] = t.x; a[am][1] = t.y; a[am][2] = t.z; a[am][3] = t.w;
            }
            #pragma unroll
            for (int bn = 0; bn < 4; bn++) {
                uint2 t = *(const uint2*)&Bs[(((wc * 4 + bn) * 4 + fk) * 32 + lane) * 2];
                b[bn][0] = t.x; b[bn][1] = t.y;
            }
            #pragma unroll
            for (int am = 0; am < 4; am++)
                #pragma unroll
                for (int bn = 0; bn < 4; bn++)
                    mma8(acc[am][bn], a[am], b[bn][0], b[bn][1]);
        }
        __syncthreads();
        if (kt + NSTG < NITER) issue(kt + NSTG);
        CP_COMMIT();
    }

    // ---- epilogue
    const int qrow = lane >> 2, qcol = (lane & 3) * 2;
    #pragma unroll
    for (int am = 0; am < 4; am++) {
        #pragma unroll
        for (int half = 0; half < 2; half++) {
            int m = m0 + (wr * 4 + am) * 16 + qrow + half * 8;
            int b_ = m >> 11, t = m & (CT - 1);
            #pragma unroll
            for (int bn = 0; bn < 4; bn++) {
                int col = n0 + (wc * 4 + bn) * 8 + qcol;
                float v0 = acc[am][bn][half * 2 + 0];
                float v1 = acc[am][bn][half * 2 + 1];
                if (mode == 0) {
                    *(float2*)&out[(size_t)m * CD + col] = make_float2(v0, v1);
                } else {
                    int h = col >> 6, d0 = col & 63;
                    int bh = b_ * CH + h;
                    if (mode <= 2) {   // RoPE for Q and K
                        int pidx = d0 >> 1;
                        float inv = exp2f(-(float)pidx * (9.965784284662087f / 32.0f));
                        float sn, cs;
                        sincosf((float)t * inv, &sn, &cs);
                        float re = v0 * cs - v1 * sn;
                        float ro = v0 * sn + v1 * cs;
                        v0 = re; v1 = ro;
                    }
                    if (mode == 1) {           // Q A-frags per (bh,qb)
                        int qb = t >> 6, tq = t & 63, mf = tq >> 4, mi = tq & 15;
                        int kf = d0 >> 3, ki = d0 & 7;
                        int ls = (mi & 7) * 4 + (ki & 3);
                        int slot = ((ki & 4) >> 1) | (mi >> 3);
                        float* p = out + ((size_t)((bh * 32 + qb) * 4 + mf) * 8 + kf) * 128
                                       + ls * 4 + slot;
                        p[0] = rna_tf32(v0); p[4] = rna_tf32(v1);
                    } else if (mode == 2) {    // K B-frags per (bh,kb)
                        int kb = t >> 6, tk = t & 63, nf = tk >> 3, ni = tk & 7;
                        int kf = d0 >> 3, ki = d0 & 7;
                        int ls = ni * 4 + (ki & 3), slot = ki >> 2;
                        float* p = out + ((size_t)((bh * 32 + kb) * 8 + kf) * 8 + nf) * 64
                                       + ls * 2 + slot;
                        p[0] = rna_tf32(v0); p[2] = rna_tf32(v1);
                    } else {                   // V B-frags per (bh,kb)
                        int kb = t >> 6, keyl = t & 63, kf = keyl >> 3, ki = keyl & 7;
                        int nf = d0 >> 3, ni = d0 & 7;
                        int ls = ni * 4 + (ki & 3), slot = ki >> 2;
                        float* p = out + ((size_t)((bh * 32 + kb) * 8 + kf) * 8 + nf) * 64
                                       + ls * 2 + slot;
                        p[0] = rna_tf32(v0); p[8] = rna_tf32(v1);
                    }
                }
            }
        }
    }
}

// ---------------------------------------------------------------------------
// Flash attention on pre-permuted fragments. Q A-frags gmem->regs directly;
// K/V tiles cp.async double-buffered. Softmax on accumulator layout;
// P C-layout -> A-frag via register shuffles. cat written as A-frags.
// ---------------------------------------------------------------------------
__global__ __launch_bounds__(128) void attn_f(
    const float* __restrict__ Qp, const float* __restrict__ Kp,
    const float* __restrict__ Vp, float* __restrict__ catp)
{
    extern __shared__ float sm[];
    const uint32_t sbase = smem_u32(sm);
    const int qb = blockIdx.x, bh = blockIdx.y;
    const int tid = threadIdx.x, wid = tid >> 5, lane = tid & 31;

    // Q A-frags straight to registers (warp wid owns mf=wid), scaled by 1/8
    uint32_t qa[8][4];
    {
        const float* qsrc = Qp + ((size_t)((bh * 32 + qb) * 4 + wid)) * 1024 + lane * 4;
        #pragma unroll
        for (int kf = 0; kf < 8; kf++) {
            float4 t = *(const float4*)(qsrc + kf * 128);
            qa[kf][0] = __float_as_uint(t.x * 0.125f);
            qa[kf][1] = __float_as_uint(t.y * 0.125f);
            qa[kf][2] = __float_as_uint(t.z * 0.125f);
            qa[kf][3] = __float_as_uint(t.w * 0.125f);
        }
    }

    auto issueKV = [&](int kb) {
        int st = kb & 1;
        uint32_t d = sbase + st * 32768;
        const float* srcK = Kp + ((size_t)(bh * 32 + kb)) * 4096;
        const float* srcV = Vp + ((size_t)(bh * 32 + kb)) * 4096;
        #pragma unroll
        for (int u = 0; u < 8; u++) {
            int idx = tid + u * 128;
            cpasync16(d + idx * 16, srcK + idx * 4);
            cpasync16(d + 16384 + idx * 16, srcV + idx * 4);
        }
    };

    issueKV(0); CP_COMMIT();

    float m_[2] = {-1e30f, -1e30f}, l_[2] = {0.0f, 0.0f};
    float O[8][4] = {};

    const int src0 = (lane & ~3) | ((lane & 3) >> 1);
    const int src2 = src0 | 2;
    const bool sel = lane & 1;
    const int row0 = wid * 16 + (lane >> 2);

    for (int kb = 0; kb <= qb; kb++) {
        if (kb < qb) issueKV(kb + 1);
        CP_COMMIT();
        CP_WAIT(1);
        __syncthreads();
        const float* Ks = sm + (kb & 1) * 8192;
        const float* Vs = Ks + 4096;

        // ---- S = Q K^T
        float S[8][4] = {};
        #pragma unroll
        for (int kf = 0; kf < 8; kf++) {
            #pragma unroll
            for (int nf = 0; nf < 8; nf++) {
                uint2 kfr = *(const uint2*)&Ks[((kf * 8 + nf) * 32 + lane) * 2];
                mma8(S[nf], qa[kf], kfr.x, kfr.y);
            }
        }

        if (kb == qb) {
            #pragma unroll
            for (int nf = 0; nf < 8; nf++)
                #pragma unroll
                for (int e = 0; e < 4; e++) {
                    int col = nf * 8 + 2 * (lane & 3) + (e & 1);
                    int row = row0 + ((e >> 1) << 3);
                    if (col > row) S[nf][e] = -1e30f;
                }
        }

        // ---- online softmax (quad-lane reductions)
        #pragma unroll
        for (int h = 0; h < 2; h++) {
            float mx = -1e30f;
            #pragma unroll
            for (int nf = 0; nf < 8; nf++)
                mx = fmaxf(mx, fmaxf(S[nf][2*h], S[nf][2*h + 1]));
            mx = fmaxf(mx, __shfl_xor_sync(0xffffffffu, mx, 1));
            mx = fmaxf(mx, __shfl_xor_sync(0xffffffffu, mx, 2));
            float mn = fmaxf(m_[h], mx);
            float sc = __expf(m_[h] - mn);
            float rs = 0.0f;
            #pragma unroll
            for (int nf = 0; nf < 8; nf++) {
                float p0 = rna_tf32(__expf(S[nf][2*h]     - mn));
                float p1 = rna_tf32(__expf(S[nf][2*h + 1] - mn));
                S[nf][2*h] = p0; S[nf][2*h + 1] = p1;
                rs += p0 + p1;
            }
            rs += __shfl_xor_sync(0xffffffffu, rs, 1);
            rs += __shfl_xor_sync(0xffffffffu, rs, 2);
            l_[h] = l_[h] * sc + rs;
            m_[h] = mn;
            #pragma unroll
            for (int nf = 0; nf < 8; nf++) { O[nf][2*h] *= sc; O[nf][2*h + 1] *= sc; }
        }

        // ---- O += P V (P -> A-frag via shfl)
        #pragma unroll
        for (int j = 0; j < 8; j++) {
            float t00 = __shfl_sync(0xffffffffu, S[j][0], src0);
            float t01 = __shfl_sync(0xffffffffu, S[j][1], src0);
            float t20 = __shfl_sync(0xffffffffu, S[j][0], src2);
            float t21 = __shfl_sync(0xffffffffu, S[j][1], src2);
            float t10 = __shfl_sync(0xffffffffu, S[j][2], src0);
            float t11 = __shfl_sync(0xffffffffu, S[j][3], src0);
            float t30 = __shfl_sync(0xffffffffu, S[j][2], src2);
            float t31 = __shfl_sync(0xffffffffu, S[j][3], src2);
            uint32_t pa[4];
            pa[0] = __float_as_uint(sel ? t01 : t00);
            pa[1] = __float_as_uint(sel ? t11 : t10);
            pa[2] = __float_as_uint(sel ? t21 : t20);
            pa[3] = __float_as_uint(sel ? t31 : t30);
            #pragma unroll
            for (int nf = 0; nf < 8; nf++) {
                uint2 vf = *(const uint2*)&Vs[((j * 8 + nf) * 32 + lane) * 2];
                mma8(O[nf], pa, vf.x, vf.y);
            }
        }
        __syncthreads();
    }

    // ---- epilogue: write cat as A-frags (feeds out-proj)
    const int b_ = bh >> 4, h = bh & 15;
    #pragma unroll
    for (int h2 = 0; h2 < 2; h2++) {
        int t = qb * 64 + wid * 16 + (lane >> 2) + h2 * 8;
        int m = b_ * CT + t;
        float inv = 1.0f / l_[h2];
        int mf = m >> 4, mi = m & 15;
        #pragma unroll
        for (int nf = 0; nf < 8; nf++) {
            int d = nf * 8 + 2 * (lane & 3);
            int kcol = h * 64 + d;
            int kf = kcol >> 3, ki = d & 7;
            int ls = (mi & 7) * 4 + (ki & 3);
            int slot = ((ki & 4) >> 1) | (mi >> 3);
            float* p = catp + ((size_t)(mf * (CD / 8) + kf) * 32 + ls) * 4 + slot;
            p[0] = rna_tf32(O[nf][2*h2]     * inv);
            p[4] = rna_tf32(O[nf][2*h2 + 1] * inv);
        }
    }
}

extern "C" void kernel_launch(void* const* d_in, const int* in_sizes, int n_in,
                              void* d_out, int out_size) {
    const float* x  = (const float*)d_in[0];
    const float* wq = (const float*)d_in[1];
    const float* wk = (const float*)d_in[2];
    const float* wv = (const float*)d_in[3];
    const float* wo = (const float*)d_in[4];
    float* out = (float*)d_out;

    float *xp, *wp, *qp, *kp, *vp, *catp;
    cudaGetSymbolAddress((void**)&xp,   g_xp);
    cudaGetSymbolAddress((void**)&wp,   g_wp);
    cudaGetSymbolAddress((void**)&qp,   g_qp);
    cudaGetSymbolAddress((void**)&kp,   g_kp);
    cudaGetSymbolAddress((void**)&vp,   g_vp);
    cudaGetSymbolAddress((void**)&catp, g_catp);

    cudaFuncSetAttribute(gemm_f, cudaFuncAttributeMaxDynamicSharedMemorySize, GEMM_SMEM);
    cudaFuncSetAttribute(attn_f, cudaFuncAttributeMaxDynamicSharedMemorySize, ATTN_SMEM);

    // prepass: tf32-round + permute to fragment order
    permA<<<(CM/16)*(CD/8)*32/256, 256>>>(x, xp);
    permB<<<(CD/8)*(CD/8)*32/256, 256>>>(wq, wp + 0*CD*CD);
    permB<<<(CD/8)*(CD/8)*32/256, 256>>>(wk, wp + 1*CD*CD);
    permB<<<(CD/8)*(CD/8)*32/256, 256>>>(wv, wp + 2*CD*CD);
    permB<<<(CD/8)*(CD/8)*32/256, 256>>>(wo, wp + 3*CD*CD);

    dim3 gg(CD / BN, CM / BM);   // (8, 32)
    gemm_f<<<gg, 256, GEMM_SMEM>>>(xp, wp + 0*CD*CD, qp, 1);   // Q + RoPE -> frags
    gemm_f<<<gg, 256, GEMM_SMEM>>>(xp, wp + 1*CD*CD, kp, 2);   // K + RoPE -> frags
    gemm_f<<<gg, 256, GEMM_SMEM>>>(xp, wp + 2*CD*CD, vp, 3);   // V -> frags

    dim3 ga(CT / 64, CB * CH);   // (32, 32)
    attn_f<<<ga, 128, ATTN_SMEM>>>(qp, kp, vp, catp);

    gemm_f<<<gg, 256, GEMM_SMEM>>>(catp, wp + 3*CD*CD, out, 0); // out-proj
}